// round 14
// baseline (speedup 1.0000x reference)
#include <cuda_runtime.h>
#include <cuda_fp16.h>
#include <math.h>
#include <stdint.h>

#define DM   1024
#define NH   16
#define HD   64
#define BB   4
#define TT   2048
#define MT   (BB * TT)        // 8192 rows

// Scratch (allocation rules: __device__ globals only) — half precision
__device__ __half g_Xh[(size_t)MT * DM];
__device__ __half g_Qh[(size_t)MT * DM];
__device__ __half g_Kh[(size_t)MT * DM];
__device__ __half g_Vh[(size_t)MT * DM];
__device__ __half g_Ch[(size_t)MT * DM];
__device__ __half g_Wqh[(size_t)DM * DM];
__device__ __half g_Wkh[(size_t)DM * DM];
__device__ __half g_Wvh[(size_t)DM * DM];
__device__ __half g_Woh[(size_t)DM * DM];

// ---------------------------------------------------------------------------
// helpers (sm_80-class — compute_103-safe, no tcgen05)
// ---------------------------------------------------------------------------
__device__ __forceinline__ void mma_f16(float4& d,
                                        uint32_t a0, uint32_t a1, uint32_t a2, uint32_t a3,
                                        uint32_t b0, uint32_t b1) {
    asm volatile(
        "mma.sync.aligned.m16n8k16.row.col.f32.f16.f16.f32 "
        "{%0,%1,%2,%3}, {%4,%5,%6,%7}, {%8,%9}, {%0,%1,%2,%3};"
        : "+f"(d.x), "+f"(d.y), "+f"(d.z), "+f"(d.w)
        : "r"(a0), "r"(a1), "r"(a2), "r"(a3), "r"(b0), "r"(b1));
}

__device__ __forceinline__ uint32_t smem_u32(const void* p) {
    uint32_t a;
    asm("{ .reg .u64 t; cvta.to.shared.u64 t, %1; cvt.u32.u64 %0, t; }"
        : "=r"(a) : "l"(p));
    return a;
}

#define LDSM_X4(r0, r1, r2, r3, addr) \
    asm volatile("ldmatrix.sync.aligned.m8n8.x4.shared.b16 {%0,%1,%2,%3}, [%4];" \
                 : "=r"(r0), "=r"(r1), "=r"(r2), "=r"(r3) : "r"(addr))

#define LDSM_X4_T(r0, r1, r2, r3, addr) \
    asm volatile("ldmatrix.sync.aligned.m8n8.x4.trans.shared.b16 {%0,%1,%2,%3}, [%4];" \
                 : "=r"(r0), "=r"(r1), "=r"(r2), "=r"(r3) : "r"(addr))

#define CP_ASYNC16(dst, src) \
    asm volatile("cp.async.cg.shared.global [%0], [%1], 16;" \
                 :: "r"(dst), "l"(src) : "memory")
#define CP_COMMIT() asm volatile("cp.async.commit_group;" ::: "memory")
#define CP_WAIT1()  asm volatile("cp.async.wait_group 1;" ::: "memory")
#define CP_WAIT0()  asm volatile("cp.async.wait_group 0;" ::: "memory")

__device__ __forceinline__ uint32_t packh2(float a, float b) {
    __half2 h = __floats2half2_rn(a, b);
    return *(uint32_t*)&h;
}

// ---------------------------------------------------------------------------
// Fused fp32->fp16 conversion of x + 4 weight matrices.
// ---------------------------------------------------------------------------
__global__ void f2h_all(const float* __restrict__ x,
                        const float* __restrict__ wq, const float* __restrict__ wk,
                        const float* __restrict__ wv, const float* __restrict__ wo)
{
    const size_t NX = (size_t)MT * DM;      // 2^23
    const size_t i = ((size_t)blockIdx.x * 256 + threadIdx.x) * 8;

    const float* s;
    __half* d;
    size_t off;
    if (i < NX) {
        s = x; d = g_Xh; off = i;
    } else {
        const size_t j = i - NX;
        const int w = (int)(j >> 20);
        off = j & 0xFFFFFu;
        switch (w) {
            case 0: s = wq; d = g_Wqh; break;
            case 1: s = wk; d = g_Wkh; break;
            case 2: s = wv; d = g_Wvh; break;
            default: s = wo; d = g_Woh; break;
        }
    }
    float4 a = *(const float4*)(s + off);
    float4 b = *(const float4*)(s + off + 4);
    uint4 o = make_uint4(packh2(a.x, a.y), packh2(a.z, a.w),
                         packh2(b.x, b.y), packh2(b.z, b.w));
    *(uint4*)(d + off) = o;
}

// ---------------------------------------------------------------------------
// fp16 tensor-core GEMM: C = A @ W^T + bias. CTA 128x128, 4 warps (64x64
// warp tiles). Stages of BK=64 (16 barrier windows instead of 32) — the
// round-13 iteration body executed twice per window with compile-time
// half*32 column offsets. 3 smem stage buffers, cp.async 2-deep, 2 CTAs/SM.
// ---------------------------------------------------------------------------
#define GST 72                              // smem row stride (halves), 144 B
#define GTILE (128 * GST * 2)               // 18432 B per A-or-W stage tile
#define GEMM_SMEM (3 * 2 * GTILE)           // 110592 B

template <int MODE>
__global__ __launch_bounds__(128, 2) void gemm_h(
    const __half* __restrict__ A,
    const __half* __restrict__ W0, const __half* __restrict__ W1, const __half* __restrict__ W2,
    const float* __restrict__ b0, const float* __restrict__ b1, const float* __restrict__ b2,
    void* o0, void* o1, void* o2)
{
    extern __shared__ __align__(16) __half gsm[];

    const int z = blockIdx.z;
    const __half* W    = (z == 0) ? W0 : (z == 1) ? W1 : W2;
    const float*  bias = (z == 0) ? b0 : (z == 1) ? b1 : b2;
    void*         outp = (z == 0) ? o0 : (z == 1) ? o1 : o2;

    const int tid  = threadIdx.x;
    const int lane = tid & 31;
    const int wid  = tid >> 5;          // 0..3
    const int wm   = (wid & 1) * 64;
    const int wn   = (wid >> 1) * 64;
    const int bm   = blockIdx.y * 128;
    const int bn   = blockIdx.x * 128;

    const uint32_t sBase = smem_u32(gsm);

    auto issue = [&](int s) {
        const int buf = s % 3;
        const int k0 = s * 64;
#pragma unroll
        for (int i = 0; i < 8; i++) {
            const int idx = tid + i * 128;   // 128 rows x 8 x 16B
            const int row = idx >> 3;
            const int c8  = idx & 7;
            const uint32_t off = (uint32_t)((row * GST + c8 * 8) * 2);
            CP_ASYNC16(sBase + buf * 2 * GTILE + off,
                       A + (size_t)(bm + row) * DM + k0 + c8 * 8);
            CP_ASYNC16(sBase + (buf * 2 + 1) * GTILE + off,
                       W + (size_t)(bn + row) * DM + k0 + c8 * 8);
        }
        CP_COMMIT();
    };

    float4 acc[4][8];
#pragma unroll
    for (int i = 0; i < 4; i++)
#pragma unroll
        for (int j = 0; j < 8; j++) acc[i][j] = make_float4(0.f, 0.f, 0.f, 0.f);

    issue(0); issue(1);

    for (int s = 0; s < 16; s++) {
        const int buf = s % 3;
        if (s < 15) { CP_WAIT1(); } else { CP_WAIT0(); }
        __syncthreads();                 // stage s ready; readers of s-1 done
        if (s + 2 < 16) issue(s + 2);    // writes buf (s-1)%3 — safe post-sync

        const uint32_t sA = sBase + buf * 2 * GTILE;
        const uint32_t sW = sA + GTILE;

        // Two BK=32 halves per window; all offsets compile-time constants.
#pragma unroll
        for (int half = 0; half < 2; half++) {
            // B fragments: 8 n-tiles, each LDSM.x4 covers this half's 2 k16 chunks
            uint32_t bf[8][4];
#pragma unroll
            for (int nt = 0; nt < 8; nt++) {
                const uint32_t baddr = sW + (uint32_t)(((wn + nt * 8 + (lane & 7)) * GST
                                         + half * 32 + ((lane >> 3) << 3)) * 2);
                LDSM_X4(bf[nt][0], bf[nt][1], bf[nt][2], bf[nt][3], baddr);
            }
            // A fragments: both k16 chunks of this half
            uint32_t af[2][4][4];
#pragma unroll
            for (int kc = 0; kc < 2; kc++)
#pragma unroll
                for (int mt = 0; mt < 4; mt++) {
                    const uint32_t aaddr = sA + (uint32_t)(((wm + mt * 16 + (lane & 15)) * GST
                                             + half * 32 + kc * 16 + ((lane >> 4) << 3)) * 2);
                    LDSM_X4(af[kc][mt][0], af[kc][mt][1], af[kc][mt][2], af[kc][mt][3], aaddr);
                }
            // 64 HMMAs, uninterrupted
#pragma unroll
            for (int kc = 0; kc < 2; kc++)
#pragma unroll
                for (int mt = 0; mt < 4; mt++)
#pragma unroll
                    for (int nt = 0; nt < 8; nt++)
                        mma_f16(acc[mt][nt],
                                af[kc][mt][0], af[kc][mt][1],
                                af[kc][mt][2], af[kc][mt][3],
                                bf[nt][2 * kc], bf[nt][2 * kc + 1]);
        }
    }

    // ---- epilogue ----
    const int lrow4 = lane >> 2;
    const int lcol4 = lane & 3;
#pragma unroll
    for (int mt = 0; mt < 4; mt++) {
        const int m0 = bm + wm + mt * 16 + lrow4;
#pragma unroll
        for (int nt = 0; nt < 8; nt++) {
            const int n0 = bn + wn + nt * 8 + lcol4 * 2;
            const float bb0 = __ldg(bias + n0);
            const float bb1 = __ldg(bias + n0 + 1);
            const float v00 = acc[mt][nt].x + bb0, v01 = acc[mt][nt].y + bb1;
            const float v10 = acc[mt][nt].z + bb0, v11 = acc[mt][nt].w + bb1;
            if (MODE == 0) {
                float* out = (float*)outp;
                *(float2*)(out + (size_t)m0 * DM + n0)       = make_float2(v00, v01);
                *(float2*)(out + (size_t)(m0 + 8) * DM + n0) = make_float2(v10, v11);
            } else {
                __half* out = (__half*)outp;
                const int h = n0 >> 6;
                const int d = n0 & 63;
                const int b_0 = m0 / TT,       t0 = m0 % TT;
                const int b_1 = (m0 + 8) / TT, t1 = (m0 + 8) % TT;
                *(uint32_t*)(out + ((size_t)(b_0 * NH + h) * TT + t0) * HD + d) = packh2(v00, v01);
                *(uint32_t*)(out + ((size_t)(b_1 * NH + h) * TT + t1) * HD + d) = packh2(v10, v11);
            }
        }
    }
}

// ---------------------------------------------------------------------------
// Causal flash attention, fp16 tensor cores (unchanged from round 13).
// BQ=128 x BK=64, 256 thr = 8 warps. P in registers. K/V triple-buffered
// cp.async. Base-2 softmax. Paired q-tiles: 512 CTAs x 34 iterations.
// ---------------------------------------------------------------------------
#define HST 72
#define KH_OFF(buf) ((128 + (buf) * 2 * 64) * HST)
#define VH_OFF(buf) (KH_OFF(buf) + 64 * HST)
#define ATT_SMEM ((128 * HST + 3 * 2 * 64 * HST) * (int)sizeof(__half))  // 73728 B
#define SCL2 0.18033688011112042f   // 0.125 * log2(e)

__global__ __launch_bounds__(256, 2) void attn_kernel()
{
    extern __shared__ __half sh[];
    const int tid  = threadIdx.x;
    const int lane = tid & 31;
    const int w    = tid >> 5;

    const int p  = blockIdx.x;       // 0..7
    const int h  = blockIdx.y;
    const int b  = blockIdx.z;
    const size_t base = (size_t)(b * NH + h) * TT * HD;

    const uint32_t smem = smem_u32(sh);
    const int g = lane >> 2;
    const int ccol = 2 * (lane & 3);

    for (int tt = 0; tt < 2; tt++) {
        const int qt = tt ? (15 - p) : p;
        const int q0 = qt * 128;
        const int ntiles = 2 * qt + 2;

        auto issue_kv = [&](int j) {
            const int buf = j % 3;
#pragma unroll
            for (int i = 0; i < 2; i++) {
                const int idx = tid + i * 256;   // 64 rows x 8 x 16B
                const int row = idx >> 3;
                const int c8  = idx & 7;
                const uint32_t off = (uint32_t)((row * HST + c8 * 8) * 2);
                CP_ASYNC16(smem + KH_OFF(buf) * 2 + off,
                           g_Kh + base + (size_t)(j * 64 + row) * HD + c8 * 8);
                CP_ASYNC16(smem + VH_OFF(buf) * 2 + off,
                           g_Vh + base + (size_t)(j * 64 + row) * HD + c8 * 8);
            }
            CP_COMMIT();
        };

        issue_kv(0);
        issue_kv(1);   // ntiles >= 2 always

        // ---- Load Q tile (128 x 64 halves) ----
#pragma unroll
        for (int i = 0; i < 4; i++) {
            const int idx = tid + i * 256;
            const int q   = idx >> 3;
            const int c8  = idx & 7;
            uint4 v = *(const uint4*)(g_Qh + base + (size_t)(q0 + q) * HD + c8 * 8);
            *(uint4*)&sh[q * HST + c8 * 8] = v;
        }
        __syncthreads();

        uint32_t qa[4][4];
        {
            const uint32_t rbase = smem + (uint32_t)(((w * 16 + (lane & 15)) * HST
                                   + ((lane >> 4) << 3)) * 2);
#pragma unroll
            for (int kk = 0; kk < 4; kk++)
                LDSM_X4(qa[kk][0], qa[kk][1], qa[kk][2], qa[kk][3], rbase + kk * 32);
        }

        float4 o[8];
#pragma unroll
        for (int i = 0; i < 8; i++) o[i] = make_float4(0.f, 0.f, 0.f, 0.f);
        float m0 = -1e30f, m1 = -1e30f, l0 = 0.f, l1 = 0.f;

        const int qrow0 = q0 + w * 16 + g;
        const int qrow1 = qrow0 + 8;

        for (int j = 0; j < ntiles; j++) {
            const int buf = j % 3;
            if (j + 1 < ntiles) { CP_WAIT1(); } else { CP_WAIT0(); }
            __syncthreads();                      // buf j ready; readers of j-1 done
            if (j + 2 < ntiles) issue_kv(j + 2);  // writes buf (j-1)%3 — safe

            const uint32_t sK = smem + KH_OFF(buf) * 2;
            const uint32_t sV = smem + VH_OFF(buf) * 2;

            // ---- S = Q @ K^T ----
            float4 s[8];
#pragma unroll
            for (int kn = 0; kn < 8; kn++) s[kn] = make_float4(0.f, 0.f, 0.f, 0.f);
#pragma unroll
            for (int kn = 0; kn < 8; kn++) {
                uint32_t kb[2][4];
                const uint32_t kaddr = sK + (uint32_t)(((kn * 8 + (lane & 7)) * HST
                                       + ((lane >> 3) << 3)) * 2);
                LDSM_X4(kb[0][0], kb[0][1], kb[0][2], kb[0][3], kaddr);
                LDSM_X4(kb[1][0], kb[1][1], kb[1][2], kb[1][3], kaddr + 64);
#pragma unroll
                for (int kk = 0; kk < 4; kk++)
                    mma_f16(s[kn], qa[kk][0], qa[kk][1], qa[kk][2], qa[kk][3],
                            kb[kk >> 1][2 * (kk & 1)], kb[kk >> 1][2 * (kk & 1) + 1]);
            }

            // ---- scale (base-2 domain) + causal mask ----
            const bool need_mask = (j >= 2 * qt);
#pragma unroll
            for (int kn = 0; kn < 8; kn++) {
                s[kn].x *= SCL2; s[kn].y *= SCL2; s[kn].z *= SCL2; s[kn].w *= SCL2;
                if (need_mask) {
                    const int col = j * 64 + kn * 8 + ccol;
                    if (col     > qrow0) s[kn].x = -1e30f;
                    if (col + 1 > qrow0) s[kn].y = -1e30f;
                    if (col     > qrow1) s[kn].z = -1e30f;
                    if (col + 1 > qrow1) s[kn].w = -1e30f;
                }
            }

            // ---- online softmax (fp32, base-2) ----
            float mx0 = -1e30f, mx1 = -1e30f;
#pragma unroll
            for (int kn = 0; kn < 8; kn++) {
                mx0 = fmaxf(mx0, fmaxf(s[kn].x, s[kn].y));
                mx1 = fmaxf(mx1, fmaxf(s[kn].z, s[kn].w));
            }
            mx0 = fmaxf(mx0, __shfl_xor_sync(0xffffffffu, mx0, 1));
            mx0 = fmaxf(mx0, __shfl_xor_sync(0xffffffffu, mx0, 2));
            mx1 = fmaxf(mx1, __shfl_xor_sync(0xffffffffu, mx1, 1));
            mx1 = fmaxf(mx1, __shfl_xor_sync(0xffffffffu, mx1, 2));
            const float mn0 = fmaxf(m0, mx0);
            const float mn1 = fmaxf(m1, mx1);

            float ps0 = 0.f, ps1 = 0.f;
#pragma unroll
            for (int kn = 0; kn < 8; kn++) {
                s[kn].x = exp2f(s[kn].x - mn0);
                s[kn].y = exp2f(s[kn].y - mn0);
                s[kn].z = exp2f(s[kn].z - mn1);
                s[kn].w = exp2f(s[kn].w - mn1);
                ps0 += s[kn].x + s[kn].y;
                ps1 += s[kn].z + s[kn].w;
            }
            ps0 += __shfl_xor_sync(0xffffffffu, ps0, 1);
            ps0 += __shfl_xor_sync(0xffffffffu, ps0, 2);
            ps1 += __shfl_xor_sync(0xffffffffu, ps1, 1);
            ps1 += __shfl_xor_sync(0xffffffffu, ps1, 2);

            const float corr0 = exp2f(m0 - mn0);
            const float corr1 = exp2f(m1 - mn1);
            l0 = l0 * corr0 + ps0;  m0 = mn0;
            l1 = l1 * corr1 + ps1;  m1 = mn1;
#pragma unroll
            for (int i = 0; i < 8; i++) {
                o[i].x *= corr0; o[i].y *= corr0;
                o[i].z *= corr1; o[i].w *= corr1;
            }

            // ---- P fragments directly from S accumulators ----
            uint32_t pa[4][4];
#pragma unroll
            for (int t = 0; t < 4; t++) {
                pa[t][0] = packh2(s[2 * t].x,     s[2 * t].y);
                pa[t][1] = packh2(s[2 * t].z,     s[2 * t].w);
                pa[t][2] = packh2(s[2 * t + 1].x, s[2 * t + 1].y);
                pa[t][3] = packh2(s[2 * t + 1].z, s[2 * t + 1].w);
            }

            // ---- O += P @ V ----
#pragma unroll
            for (int vn = 0; vn < 8; vn++) {
                uint32_t vb[2][4];
#pragma unroll
                for (int c = 0; c < 2; c++) {
                    const uint32_t vaddr = sV + (uint32_t)(((c * 32 + (lane & 31)) * HST
                                            + vn * 8) * 2);
                    LDSM_X4_T(vb[c][0], vb[c][1], vb[c][2], vb[c][3], vaddr);
                }
#pragma unroll
                for (int t = 0; t < 4; t++)
                    mma_f16(o[vn], pa[t][0], pa[t][1], pa[t][2], pa[t][3],
                            vb[t >> 1][2 * (t & 1)], vb[t >> 1][2 * (t & 1) + 1]);
            }
        }

        // ---- normalize + write ctx (B,T,D) as half ----
        const float inv0 = 1.f / l0;
        const float inv1 = 1.f / l1;
#pragma unroll
        for (int vn = 0; vn < 8; vn++) {
            const int d = vn * 8 + ccol;
            *(uint32_t*)(g_Ch + ((size_t)(b * TT + qrow0)) * DM + h * HD + d) =
                packh2(o[vn].x * inv0, o[vn].y * inv0);
            *(uint32_t*)(g_Ch + ((size_t)(b * TT + qrow1)) * DM + h * HD + d) =
                packh2(o[vn].z * inv1, o[vn].w * inv1);
        }
        __syncthreads();   // all smem reads done before next tile reuses buffers
    }
}

// ---------------------------------------------------------------------------
extern "C" void kernel_launch(void* const* d_in, const int* in_sizes, int n_in,
                              void* d_out, int out_size)
{
    const float* x  = (const float*)d_in[0];
    const float* Wq = (const float*)d_in[1];
    const float* bq = (const float*)d_in[2];
    const float* Wk = (const float*)d_in[3];
    const float* bk = (const float*)d_in[4];
    const float* Wv = (const float*)d_in[5];
    const float* bv = (const float*)d_in[6];
    const float* Wo = (const float*)d_in[7];
    const float* bo = (const float*)d_in[8];
    float* out = (float*)d_out;

    __half *Xp, *Qp, *Kp, *Vp, *Cp, *Wqp, *Wkp, *Wvp, *Wop;
    cudaGetSymbolAddress((void**)&Xp,  g_Xh);
    cudaGetSymbolAddress((void**)&Qp,  g_Qh);
    cudaGetSymbolAddress((void**)&Kp,  g_Kh);
    cudaGetSymbolAddress((void**)&Vp,  g_Vh);
    cudaGetSymbolAddress((void**)&Cp,  g_Ch);
    cudaGetSymbolAddress((void**)&Wqp, g_Wqh);
    cudaGetSymbolAddress((void**)&Wkp, g_Wkh);
    cudaGetSymbolAddress((void**)&Wvp, g_Wvh);
    cudaGetSymbolAddress((void**)&Wop, g_Woh);

    cudaFuncSetAttribute(gemm_h<0>, cudaFuncAttributeMaxDynamicSharedMemorySize, GEMM_SMEM);
    cudaFuncSetAttribute(gemm_h<1>, cudaFuncAttributeMaxDynamicSharedMemorySize, GEMM_SMEM);
    cudaFuncSetAttribute(attn_kernel, cudaFuncAttributeMaxDynamicSharedMemorySize, ATT_SMEM);

    // ---- preconvert to half (x + 4 weights, one launch) ----
    const size_t ntot = (size_t)MT * DM + 4 * (size_t)DM * DM;  // 12.58M
    f2h_all<<<(int)(ntot / 8 / 256), 256>>>(x, Wq, Wk, Wv, Wo);

    // ---- fused QKV projections ----
    dim3 gq(DM / 128, MT / 128, 3);
    gemm_h<1><<<gq, 128, GEMM_SMEM>>>(Xp, Wqp, Wkp, Wvp, bq, bk, bv, Qp, Kp, Vp);

    // ---- attention (paired q-tiles, perfectly balanced) ----
    dim3 agrid(8, NH, BB);            // 512 CTAs x 34 iterations each
    attn_kernel<<<agrid, 256, ATT_SMEM>>>();

    // ---- output projection ----
    dim3 go(DM / 128, MT / 128, 1);
    gemm_h<0><<<go, 128, GEMM_SMEM>>>(Cp, Wop, Wop, Wop, bo, bo, bo, out, out, out);
}

// round 15
// speedup vs baseline: 1.5643x; 1.5643x over previous
#include <cuda_runtime.h>
#include <cuda_fp16.h>
#include <math.h>
#include <stdint.h>

#define DM   1024
#define NH   16
#define HD   64
#define BB   4
#define TT   2048
#define MT   (BB * TT)        // 8192 rows

// Scratch (allocation rules: __device__ globals only) — half precision
__device__ __half g_Xh[(size_t)MT * DM];
__device__ __half g_Qh[(size_t)MT * DM];
__device__ __half g_Kh[(size_t)MT * DM];
__device__ __half g_Vh[(size_t)MT * DM];
__device__ __half g_Ch[(size_t)MT * DM];
__device__ __half g_Wqh[(size_t)DM * DM];
__device__ __half g_Wkh[(size_t)DM * DM];
__device__ __half g_Wvh[(size_t)DM * DM];
__device__ __half g_Woh[(size_t)DM * DM];

#define SCL2 0.18033688011112042f   // 0.125 * log2(e), folded into Q projection

// ---------------------------------------------------------------------------
// helpers (sm_80-class — compute_103-safe, no tcgen05)
// ---------------------------------------------------------------------------
__device__ __forceinline__ void mma_f16(float4& d,
                                        uint32_t a0, uint32_t a1, uint32_t a2, uint32_t a3,
                                        uint32_t b0, uint32_t b1) {
    asm volatile(
        "mma.sync.aligned.m16n8k16.row.col.f32.f16.f16.f32 "
        "{%0,%1,%2,%3}, {%4,%5,%6,%7}, {%8,%9}, {%0,%1,%2,%3};"
        : "+f"(d.x), "+f"(d.y), "+f"(d.z), "+f"(d.w)
        : "r"(a0), "r"(a1), "r"(a2), "r"(a3), "r"(b0), "r"(b1));
}

__device__ __forceinline__ uint32_t smem_u32(const void* p) {
    uint32_t a;
    asm("{ .reg .u64 t; cvta.to.shared.u64 t, %1; cvt.u32.u64 %0, t; }"
        : "=r"(a) : "l"(p));
    return a;
}

#define LDSM_X4(r0, r1, r2, r3, addr) \
    asm volatile("ldmatrix.sync.aligned.m8n8.x4.shared.b16 {%0,%1,%2,%3}, [%4];" \
                 : "=r"(r0), "=r"(r1), "=r"(r2), "=r"(r3) : "r"(addr))

#define LDSM_X4_T(r0, r1, r2, r3, addr) \
    asm volatile("ldmatrix.sync.aligned.m8n8.x4.trans.shared.b16 {%0,%1,%2,%3}, [%4];" \
                 : "=r"(r0), "=r"(r1), "=r"(r2), "=r"(r3) : "r"(addr))

#define CP_ASYNC16(dst, src) \
    asm volatile("cp.async.cg.shared.global [%0], [%1], 16;" \
                 :: "r"(dst), "l"(src) : "memory")
#define CP_COMMIT() asm volatile("cp.async.commit_group;" ::: "memory")
#define CP_WAIT1()  asm volatile("cp.async.wait_group 1;" ::: "memory")
#define CP_WAIT0()  asm volatile("cp.async.wait_group 0;" ::: "memory")

__device__ __forceinline__ uint32_t packh2(float a, float b) {
    __half2 h = __floats2half2_rn(a, b);
    return *(uint32_t*)&h;
}

// ---------------------------------------------------------------------------
// Fused fp32->fp16 conversion of x + 4 weight matrices.
// ---------------------------------------------------------------------------
__global__ void f2h_all(const float* __restrict__ x,
                        const float* __restrict__ wq, const float* __restrict__ wk,
                        const float* __restrict__ wv, const float* __restrict__ wo)
{
    const size_t NX = (size_t)MT * DM;      // 2^23
    const size_t i = ((size_t)blockIdx.x * 256 + threadIdx.x) * 8;

    const float* s;
    __half* d;
    size_t off;
    if (i < NX) {
        s = x; d = g_Xh; off = i;
    } else {
        const size_t j = i - NX;
        const int w = (int)(j >> 20);
        off = j & 0xFFFFFu;
        switch (w) {
            case 0: s = wq; d = g_Wqh; break;
            case 1: s = wk; d = g_Wkh; break;
            case 2: s = wv; d = g_Wvh; break;
            default: s = wo; d = g_Woh; break;
        }
    }
    float4 a = *(const float4*)(s + off);
    float4 b = *(const float4*)(s + off + 4);
    uint4 o = make_uint4(packh2(a.x, a.y), packh2(a.z, a.w),
                         packh2(b.x, b.y), packh2(b.z, b.w));
    *(uint4*)(d + off) = o;
}

// ---------------------------------------------------------------------------
// fp16 tensor-core GEMM: C = A @ W^T + bias. CTA 128x128, 4 warps (64x64
// warp tiles). Stage = BK=64 (16 barrier windows); the two BK=32 halves run
// SEQUENTIALLY (#pragma unroll 1) so fragment registers die between halves
// (r14's unrolled version spilled at 254 regs). 3 smem stage buffers,
// cp.async 2-deep, 2 CTAs/SM. z==0 in MODE 1 pre-scales output by SCL2.
// ---------------------------------------------------------------------------
#define GST 72                              // smem row stride (halves), 144 B
#define GTILE (128 * GST * 2)               // 18432 B per A-or-W stage tile
#define GEMM_SMEM (3 * 2 * GTILE)           // 110592 B

template <int MODE>
__global__ __launch_bounds__(128, 2) void gemm_h(
    const __half* __restrict__ A,
    const __half* __restrict__ W0, const __half* __restrict__ W1, const __half* __restrict__ W2,
    const float* __restrict__ b0, const float* __restrict__ b1, const float* __restrict__ b2,
    void* o0, void* o1, void* o2)
{
    extern __shared__ __align__(16) __half gsm[];

    const int z = blockIdx.z;
    const __half* W    = (z == 0) ? W0 : (z == 1) ? W1 : W2;
    const float*  bias = (z == 0) ? b0 : (z == 1) ? b1 : b2;
    void*         outp = (z == 0) ? o0 : (z == 1) ? o1 : o2;
    const float oscale = (MODE == 1 && z == 0) ? SCL2 : 1.0f;

    const int tid  = threadIdx.x;
    const int lane = tid & 31;
    const int wid  = tid >> 5;          // 0..3
    const int wm   = (wid & 1) * 64;
    const int wn   = (wid >> 1) * 64;
    const int bm   = blockIdx.y * 128;
    const int bn   = blockIdx.x * 128;

    const uint32_t sBase = smem_u32(gsm);

    auto issue = [&](int s) {
        const int buf = s % 3;
        const int k0 = s * 64;
#pragma unroll
        for (int i = 0; i < 8; i++) {
            const int idx = tid + i * 128;   // 128 rows x 8 x 16B
            const int row = idx >> 3;
            const int c8  = idx & 7;
            const uint32_t off = (uint32_t)((row * GST + c8 * 8) * 2);
            CP_ASYNC16(sBase + buf * 2 * GTILE + off,
                       A + (size_t)(bm + row) * DM + k0 + c8 * 8);
            CP_ASYNC16(sBase + (buf * 2 + 1) * GTILE + off,
                       W + (size_t)(bn + row) * DM + k0 + c8 * 8);
        }
        CP_COMMIT();
    };

    float4 acc[4][8];
#pragma unroll
    for (int i = 0; i < 4; i++)
#pragma unroll
        for (int j = 0; j < 8; j++) acc[i][j] = make_float4(0.f, 0.f, 0.f, 0.f);

    issue(0); issue(1);

    for (int s = 0; s < 16; s++) {
        const int buf = s % 3;
        if (s < 15) { CP_WAIT1(); } else { CP_WAIT0(); }
        __syncthreads();                 // stage s ready; readers of s-1 done
        if (s + 2 < 16) issue(s + 2);    // writes buf (s-1)%3 — safe post-sync

        // Two BK=32 halves, SEQUENTIAL (unroll 1): fragments die between
        // halves, keeping register peak at the r13 level (~214).
#pragma unroll 1
        for (int half = 0; half < 2; half++) {
            const uint32_t sA = sBase + buf * 2 * GTILE + (uint32_t)half * 64u;
            const uint32_t sW = sA + GTILE;

            // B fragments: 8 n-tiles, each LDSM.x4 covers this half's 2 k16 chunks
            uint32_t bf[8][4];
#pragma unroll
            for (int nt = 0; nt < 8; nt++) {
                const uint32_t baddr = sW + (uint32_t)(((wn + nt * 8 + (lane & 7)) * GST
                                         + ((lane >> 3) << 3)) * 2);
                LDSM_X4(bf[nt][0], bf[nt][1], bf[nt][2], bf[nt][3], baddr);
            }
            // A fragments: both k16 chunks of this half
            uint32_t af[2][4][4];
#pragma unroll
            for (int kc = 0; kc < 2; kc++)
#pragma unroll
                for (int mt = 0; mt < 4; mt++) {
                    const uint32_t aaddr = sA + (uint32_t)(((wm + mt * 16 + (lane & 15)) * GST
                                             + kc * 16 + ((lane >> 4) << 3)) * 2);
                    LDSM_X4(af[kc][mt][0], af[kc][mt][1], af[kc][mt][2], af[kc][mt][3], aaddr);
                }
            // 64 HMMAs, uninterrupted
#pragma unroll
            for (int kc = 0; kc < 2; kc++)
#pragma unroll
                for (int mt = 0; mt < 4; mt++)
#pragma unroll
                    for (int nt = 0; nt < 8; nt++)
                        mma_f16(acc[mt][nt],
                                af[kc][mt][0], af[kc][mt][1],
                                af[kc][mt][2], af[kc][mt][3],
                                bf[nt][2 * kc], bf[nt][2 * kc + 1]);
        }
    }

    // ---- epilogue ----
    const int lrow4 = lane >> 2;
    const int lcol4 = lane & 3;
#pragma unroll
    for (int mt = 0; mt < 4; mt++) {
        const int m0 = bm + wm + mt * 16 + lrow4;
#pragma unroll
        for (int nt = 0; nt < 8; nt++) {
            const int n0 = bn + wn + nt * 8 + lcol4 * 2;
            const float bb0 = __ldg(bias + n0);
            const float bb1 = __ldg(bias + n0 + 1);
            const float v00 = (acc[mt][nt].x + bb0) * oscale;
            const float v01 = (acc[mt][nt].y + bb1) * oscale;
            const float v10 = (acc[mt][nt].z + bb0) * oscale;
            const float v11 = (acc[mt][nt].w + bb1) * oscale;
            if (MODE == 0) {
                float* out = (float*)outp;
                *(float2*)(out + (size_t)m0 * DM + n0)       = make_float2(v00, v01);
                *(float2*)(out + (size_t)(m0 + 8) * DM + n0) = make_float2(v10, v11);
            } else {
                __half* out = (__half*)outp;
                const int h = n0 >> 6;
                const int d = n0 & 63;
                const int b_0 = m0 / TT,       t0 = m0 % TT;
                const int b_1 = (m0 + 8) / TT, t1 = (m0 + 8) % TT;
                *(uint32_t*)(out + ((size_t)(b_0 * NH + h) * TT + t0) * HD + d) = packh2(v00, v01);
                *(uint32_t*)(out + ((size_t)(b_1 * NH + h) * TT + t1) * HD + d) = packh2(v10, v11);
            }
        }
    }
}

// ---------------------------------------------------------------------------
// Causal flash attention, fp16 tensor cores. BQ=128 x BK=64, 256 thr = 8
// warps. P in registers. K/V triple-buffered cp.async. Base-2 softmax with
// the scale pre-folded into Q (no per-iter FMULs). Paired q-tiles:
// 512 CTAs x 34 iterations, perfectly balanced.
// ---------------------------------------------------------------------------
#define HST 72
#define KH_OFF(buf) ((128 + (buf) * 2 * 64) * HST)
#define VH_OFF(buf) (KH_OFF(buf) + 64 * HST)
#define ATT_SMEM ((128 * HST + 3 * 2 * 64 * HST) * (int)sizeof(__half))  // 73728 B

__global__ __launch_bounds__(256, 2) void attn_kernel()
{
    extern __shared__ __half sh[];
    const int tid  = threadIdx.x;
    const int lane = tid & 31;
    const int w    = tid >> 5;

    const int p  = blockIdx.x;       // 0..7
    const int h  = blockIdx.y;
    const int b  = blockIdx.z;
    const size_t base = (size_t)(b * NH + h) * TT * HD;

    const uint32_t smem = smem_u32(sh);
    const int g = lane >> 2;
    const int ccol = 2 * (lane & 3);

    for (int tt = 0; tt < 2; tt++) {
        const int qt = tt ? (15 - p) : p;
        const int q0 = qt * 128;
        const int ntiles = 2 * qt + 2;

        auto issue_kv = [&](int j) {
            const int buf = j % 3;
#pragma unroll
            for (int i = 0; i < 2; i++) {
                const int idx = tid + i * 256;   // 64 rows x 8 x 16B
                const int row = idx >> 3;
                const int c8  = idx & 7;
                const uint32_t off = (uint32_t)((row * HST + c8 * 8) * 2);
                CP_ASYNC16(smem + KH_OFF(buf) * 2 + off,
                           g_Kh + base + (size_t)(j * 64 + row) * HD + c8 * 8);
                CP_ASYNC16(smem + VH_OFF(buf) * 2 + off,
                           g_Vh + base + (size_t)(j * 64 + row) * HD + c8 * 8);
            }
            CP_COMMIT();
        };

        issue_kv(0);
        issue_kv(1);   // ntiles >= 2 always

        // ---- Load Q tile (128 x 64 halves) ----
#pragma unroll
        for (int i = 0; i < 4; i++) {
            const int idx = tid + i * 256;
            const int q   = idx >> 3;
            const int c8  = idx & 7;
            uint4 v = *(const uint4*)(g_Qh + base + (size_t)(q0 + q) * HD + c8 * 8);
            *(uint4*)&sh[q * HST + c8 * 8] = v;
        }
        __syncthreads();

        uint32_t qa[4][4];
        {
            const uint32_t rbase = smem + (uint32_t)(((w * 16 + (lane & 15)) * HST
                                   + ((lane >> 4) << 3)) * 2);
#pragma unroll
            for (int kk = 0; kk < 4; kk++)
                LDSM_X4(qa[kk][0], qa[kk][1], qa[kk][2], qa[kk][3], rbase + kk * 32);
        }

        float4 o[8];
#pragma unroll
        for (int i = 0; i < 8; i++) o[i] = make_float4(0.f, 0.f, 0.f, 0.f);
        float m0 = -1e30f, m1 = -1e30f, l0 = 0.f, l1 = 0.f;

        const int qrow0 = q0 + w * 16 + g;
        const int qrow1 = qrow0 + 8;

        for (int j = 0; j < ntiles; j++) {
            const int buf = j % 3;
            if (j + 1 < ntiles) { CP_WAIT1(); } else { CP_WAIT0(); }
            __syncthreads();                      // buf j ready; readers of j-1 done
            if (j + 2 < ntiles) issue_kv(j + 2);  // writes buf (j-1)%3 — safe

            const uint32_t sK = smem + KH_OFF(buf) * 2;
            const uint32_t sV = smem + VH_OFF(buf) * 2;

            // ---- S = Q @ K^T (already in base-2 scaled domain via Q) ----
            float4 s[8];
#pragma unroll
            for (int kn = 0; kn < 8; kn++) s[kn] = make_float4(0.f, 0.f, 0.f, 0.f);
#pragma unroll
            for (int kn = 0; kn < 8; kn++) {
                uint32_t kb[2][4];
                const uint32_t kaddr = sK + (uint32_t)(((kn * 8 + (lane & 7)) * HST
                                       + ((lane >> 3) << 3)) * 2);
                LDSM_X4(kb[0][0], kb[0][1], kb[0][2], kb[0][3], kaddr);
                LDSM_X4(kb[1][0], kb[1][1], kb[1][2], kb[1][3], kaddr + 64);
#pragma unroll
                for (int kk = 0; kk < 4; kk++)
                    mma_f16(s[kn], qa[kk][0], qa[kk][1], qa[kk][2], qa[kk][3],
                            kb[kk >> 1][2 * (kk & 1)], kb[kk >> 1][2 * (kk & 1) + 1]);
            }

            // ---- causal mask (last two key tiles only) ----
            const bool need_mask = (j >= 2 * qt);
            if (need_mask) {
#pragma unroll
                for (int kn = 0; kn < 8; kn++) {
                    const int col = j * 64 + kn * 8 + ccol;
                    if (col     > qrow0) s[kn].x = -1e30f;
                    if (col + 1 > qrow0) s[kn].y = -1e30f;
                    if (col     > qrow1) s[kn].z = -1e30f;
                    if (col + 1 > qrow1) s[kn].w = -1e30f;
                }
            }

            // ---- online softmax (fp32, base-2) ----
            float mx0 = -1e30f, mx1 = -1e30f;
#pragma unroll
            for (int kn = 0; kn < 8; kn++) {
                mx0 = fmaxf(mx0, fmaxf(s[kn].x, s[kn].y));
                mx1 = fmaxf(mx1, fmaxf(s[kn].z, s[kn].w));
            }
            mx0 = fmaxf(mx0, __shfl_xor_sync(0xffffffffu, mx0, 1));
            mx0 = fmaxf(mx0, __shfl_xor_sync(0xffffffffu, mx0, 2));
            mx1 = fmaxf(mx1, __shfl_xor_sync(0xffffffffu, mx1, 1));
            mx1 = fmaxf(mx1, __shfl_xor_sync(0xffffffffu, mx1, 2));
            const float mn0 = fmaxf(m0, mx0);
            const float mn1 = fmaxf(m1, mx1);

            float ps0 = 0.f, ps1 = 0.f;
#pragma unroll
            for (int kn = 0; kn < 8; kn++) {
                s[kn].x = exp2f(s[kn].x - mn0);
                s[kn].y = exp2f(s[kn].y - mn0);
                s[kn].z = exp2f(s[kn].z - mn1);
                s[kn].w = exp2f(s[kn].w - mn1);
                ps0 += s[kn].x + s[kn].y;
                ps1 += s[kn].z + s[kn].w;
            }
            ps0 += __shfl_xor_sync(0xffffffffu, ps0, 1);
            ps0 += __shfl_xor_sync(0xffffffffu, ps0, 2);
            ps1 += __shfl_xor_sync(0xffffffffu, ps1, 1);
            ps1 += __shfl_xor_sync(0xffffffffu, ps1, 2);

            const float corr0 = exp2f(m0 - mn0);
            const float corr1 = exp2f(m1 - mn1);
            l0 = l0 * corr0 + ps0;  m0 = mn0;
            l1 = l1 * corr1 + ps1;  m1 = mn1;
#pragma unroll
            for (int i = 0; i < 8; i++) {
                o[i].x *= corr0; o[i].y *= corr0;
                o[i].z *= corr1; o[i].w *= corr1;
            }

            // ---- P fragments directly from S accumulators ----
            uint32_t pa[4][4];
#pragma unroll
            for (int t = 0; t < 4; t++) {
                pa[t][0] = packh2(s[2 * t].x,     s[2 * t].y);
                pa[t][1] = packh2(s[2 * t].z,     s[2 * t].w);
                pa[t][2] = packh2(s[2 * t + 1].x, s[2 * t + 1].y);
                pa[t][3] = packh2(s[2 * t + 1].z, s[2 * t + 1].w);
            }

            // ---- O += P @ V ----
#pragma unroll
            for (int vn = 0; vn < 8; vn++) {
                uint32_t vb[2][4];
#pragma unroll
                for (int c = 0; c < 2; c++) {
                    const uint32_t vaddr = sV + (uint32_t)(((c * 32 + (lane & 31)) * HST
                                            + vn * 8) * 2);
                    LDSM_X4_T(vb[c][0], vb[c][1], vb[c][2], vb[c][3], vaddr);
                }
#pragma unroll
                for (int t = 0; t < 4; t++)
                    mma_f16(o[vn], pa[t][0], pa[t][1], pa[t][2], pa[t][3],
                            vb[t >> 1][2 * (t & 1)], vb[t >> 1][2 * (t & 1) + 1]);
            }
        }

        // ---- normalize + write ctx (B,T,D) as half ----
        const float inv0 = 1.f / l0;
        const float inv1 = 1.f / l1;
#pragma unroll
        for (int vn = 0; vn < 8; vn++) {
            const int d = vn * 8 + ccol;
            *(uint32_t*)(g_Ch + ((size_t)(b * TT + qrow0)) * DM + h * HD + d) =
                packh2(o[vn].x * inv0, o[vn].y * inv0);
            *(uint32_t*)(g_Ch + ((size_t)(b * TT + qrow1)) * DM + h * HD + d) =
                packh2(o[vn].z * inv1, o[vn].w * inv1);
        }
        __syncthreads();   // all smem reads done before next tile reuses buffers
    }
}

// ---------------------------------------------------------------------------
extern "C" void kernel_launch(void* const* d_in, const int* in_sizes, int n_in,
                              void* d_out, int out_size)
{
    const float* x  = (const float*)d_in[0];
    const float* Wq = (const float*)d_in[1];
    const float* bq = (const float*)d_in[2];
    const float* Wk = (const float*)d_in[3];
    const float* bk = (const float*)d_in[4];
    const float* Wv = (const float*)d_in[5];
    const float* bv = (const float*)d_in[6];
    const float* Wo = (const float*)d_in[7];
    const float* bo = (const float*)d_in[8];
    float* out = (float*)d_out;

    __half *Xp, *Qp, *Kp, *Vp, *Cp, *Wqp, *Wkp, *Wvp, *Wop;
    cudaGetSymbolAddress((void**)&Xp,  g_Xh);
    cudaGetSymbolAddress((void**)&Qp,  g_Qh);
    cudaGetSymbolAddress((void**)&Kp,  g_Kh);
    cudaGetSymbolAddress((void**)&Vp,  g_Vh);
    cudaGetSymbolAddress((void**)&Cp,  g_Ch);
    cudaGetSymbolAddress((void**)&Wqp, g_Wqh);
    cudaGetSymbolAddress((void**)&Wkp, g_Wkh);
    cudaGetSymbolAddress((void**)&Wvp, g_Wvh);
    cudaGetSymbolAddress((void**)&Wop, g_Woh);

    cudaFuncSetAttribute(gemm_h<0>, cudaFuncAttributeMaxDynamicSharedMemorySize, GEMM_SMEM);
    cudaFuncSetAttribute(gemm_h<1>, cudaFuncAttributeMaxDynamicSharedMemorySize, GEMM_SMEM);
    cudaFuncSetAttribute(attn_kernel, cudaFuncAttributeMaxDynamicSharedMemorySize, ATT_SMEM);

    // ---- preconvert to half (x + 4 weights, one launch) ----
    const size_t ntot = (size_t)MT * DM + 4 * (size_t)DM * DM;  // 12.58M
    f2h_all<<<(int)(ntot / 8 / 256), 256>>>(x, Wq, Wk, Wv, Wo);

    // ---- fused QKV projections (Q output pre-scaled by SCL2) ----
    dim3 gq(DM / 128, MT / 128, 3);
    gemm_h<1><<<gq, 128, GEMM_SMEM>>>(Xp, Wqp, Wkp, Wvp, bq, bk, bv, Qp, Kp, Vp);

    // ---- attention (paired q-tiles, perfectly balanced) ----
    dim3 agrid(8, NH, BB);            // 512 CTAs x 34 iterations each
    attn_kernel<<<agrid, 256, ATT_SMEM>>>();

    // ---- output projection ----
    dim3 go(DM / 128, MT / 128, 1);
    gemm_h<0><<<go, 128, GEMM_SMEM>>>(Cp, Wop, Wop, Wop, bo, bo, bo, out, out, out);
}

// round 16
// speedup vs baseline: 1.6192x; 1.0351x over previous
#include <cuda_runtime.h>
#include <cuda_fp16.h>
#include <math.h>
#include <stdint.h>

#define DM   1024
#define NH   16
#define HD   64
#define BB   4
#define TT   2048
#define MT   (BB * TT)        // 8192 rows

// Scratch (allocation rules: __device__ globals only) — half precision
__device__ __half g_Xh[(size_t)MT * DM];
__device__ __half g_Qh[(size_t)MT * DM];
__device__ __half g_Kh[(size_t)MT * DM];
__device__ __half g_Vh[(size_t)MT * DM];
__device__ __half g_Ch[(size_t)MT * DM];
__device__ __half g_Wqh[(size_t)DM * DM];
__device__ __half g_Wkh[(size_t)DM * DM];
__device__ __half g_Wvh[(size_t)DM * DM];
__device__ __half g_Woh[(size_t)DM * DM];

#define SCL2 0.18033688011112042f   // 0.125 * log2(e), folded into Q projection

// ---------------------------------------------------------------------------
// helpers (sm_80-class — compute_103-safe, no tcgen05)
// ---------------------------------------------------------------------------
__device__ __forceinline__ void mma_f16(float4& d,
                                        uint32_t a0, uint32_t a1, uint32_t a2, uint32_t a3,
                                        uint32_t b0, uint32_t b1) {
    asm volatile(
        "mma.sync.aligned.m16n8k16.row.col.f32.f16.f16.f32 "
        "{%0,%1,%2,%3}, {%4,%5,%6,%7}, {%8,%9}, {%0,%1,%2,%3};"
        : "+f"(d.x), "+f"(d.y), "+f"(d.z), "+f"(d.w)
        : "r"(a0), "r"(a1), "r"(a2), "r"(a3), "r"(b0), "r"(b1));
}

__device__ __forceinline__ uint32_t smem_u32(const void* p) {
    uint32_t a;
    asm("{ .reg .u64 t; cvta.to.shared.u64 t, %1; cvt.u32.u64 %0, t; }"
        : "=r"(a) : "l"(p));
    return a;
}

#define LDSM_X4(r0, r1, r2, r3, addr) \
    asm volatile("ldmatrix.sync.aligned.m8n8.x4.shared.b16 {%0,%1,%2,%3}, [%4];" \
                 : "=r"(r0), "=r"(r1), "=r"(r2), "=r"(r3) : "r"(addr))

#define LDSM_X4_T(r0, r1, r2, r3, addr) \
    asm volatile("ldmatrix.sync.aligned.m8n8.x4.trans.shared.b16 {%0,%1,%2,%3}, [%4];" \
                 : "=r"(r0), "=r"(r1), "=r"(r2), "=r"(r3) : "r"(addr))

#define CP_ASYNC16(dst, src) \
    asm volatile("cp.async.cg.shared.global [%0], [%1], 16;" \
                 :: "r"(dst), "l"(src) : "memory")
#define CP_COMMIT() asm volatile("cp.async.commit_group;" ::: "memory")
#define CP_WAIT2()  asm volatile("cp.async.wait_group 2;" ::: "memory")
#define CP_WAIT1()  asm volatile("cp.async.wait_group 1;" ::: "memory")
#define CP_WAIT0()  asm volatile("cp.async.wait_group 0;" ::: "memory")

__device__ __forceinline__ uint32_t packh2(float a, float b) {
    __half2 h = __floats2half2_rn(a, b);
    return *(uint32_t*)&h;
}

// fp16x2 exp2: one MUFU op for two elements.
__device__ __forceinline__ uint32_t ex2_f16x2(float lo, float hi) {
    uint32_t r;
    asm("{ .reg .b32 t;\n\t"
        "  cvt.rn.f16x2.f32 t, %2, %1;\n\t"   // packs {hi_arg->upper? order: d = {b, a}} -> t = (hi<<16)|lo
        "  ex2.approx.f16x2 %0, t; }"
        : "=r"(r) : "f"(lo), "f"(hi));
    return r;
}

__device__ __forceinline__ float2 h2_to_f2(uint32_t h) {
    __half2 hh = *(__half2*)&h;
    return __half22float2(hh);
}

// ---------------------------------------------------------------------------
// Fused fp32->fp16 conversion of x + 4 weight matrices.
// ---------------------------------------------------------------------------
__global__ void f2h_all(const float* __restrict__ x,
                        const float* __restrict__ wq, const float* __restrict__ wk,
                        const float* __restrict__ wv, const float* __restrict__ wo)
{
    const size_t NX = (size_t)MT * DM;      // 2^23
    const size_t i = ((size_t)blockIdx.x * 256 + threadIdx.x) * 8;

    const float* s;
    __half* d;
    size_t off;
    if (i < NX) {
        s = x; d = g_Xh; off = i;
    } else {
        const size_t j = i - NX;
        const int w = (int)(j >> 20);
        off = j & 0xFFFFFu;
        switch (w) {
            case 0: s = wq; d = g_Wqh; break;
            case 1: s = wk; d = g_Wkh; break;
            case 2: s = wv; d = g_Wvh; break;
            default: s = wo; d = g_Woh; break;
        }
    }
    float4 a = *(const float4*)(s + off);
    float4 b = *(const float4*)(s + off + 4);
    uint4 o = make_uint4(packh2(a.x, a.y), packh2(a.z, a.w),
                         packh2(b.x, b.y), packh2(b.z, b.w));
    *(uint4*)(d + off) = o;
}

// ---------------------------------------------------------------------------
// fp16 tensor-core GEMM (r13 core, proven): C = A @ W^T + bias.
// CTA 128x128, BK=32, 4 warps (64x64 warp tiles), 4-buffer / 3-deep cp.async,
// one __syncthreads per iteration, 2 CTAs/SM. A fragments (both k16 chunks)
// hoisted before the MMA block. z==0 in MODE 1 pre-scales output by SCL2.
// ---------------------------------------------------------------------------
#define GST 40                             // smem stride (halves), 80 B
#define GTILE 10240                        // one A-or-W tile: 128*GST*2 bytes
#define GEMM_SMEM (4 * 2 * GTILE)          // 81920 B

template <int MODE>
__global__ __launch_bounds__(128, 2) void gemm_h(
    const __half* __restrict__ A,
    const __half* __restrict__ W0, const __half* __restrict__ W1, const __half* __restrict__ W2,
    const float* __restrict__ b0, const float* __restrict__ b1, const float* __restrict__ b2,
    void* o0, void* o1, void* o2)
{
    extern __shared__ __align__(16) __half gsm[];

    const int z = blockIdx.z;
    const __half* W    = (z == 0) ? W0 : (z == 1) ? W1 : W2;
    const float*  bias = (z == 0) ? b0 : (z == 1) ? b1 : b2;
    void*         outp = (z == 0) ? o0 : (z == 1) ? o1 : o2;
    const float oscale = (MODE == 1 && z == 0) ? SCL2 : 1.0f;

    const int tid  = threadIdx.x;
    const int lane = tid & 31;
    const int wid  = tid >> 5;          // 0..3
    const int wm   = (wid & 1) * 64;
    const int wn   = (wid >> 1) * 64;
    const int bm   = blockIdx.y * 128;
    const int bn   = blockIdx.x * 128;

    const uint32_t sBase = smem_u32(gsm);

    auto issue = [&](int c) {
        const int buf = c & 3;
        const int k0 = c * 32;
#pragma unroll
        for (int i = 0; i < 4; i++) {
            const int idx = tid + i * 128;   // 128 rows x 4 x 16B
            const int row = idx >> 2;
            const int c4  = idx & 3;
            const uint32_t off = (uint32_t)((row * GST + c4 * 8) * 2);
            CP_ASYNC16(sBase + buf * 2 * GTILE + off,
                       A + (size_t)(bm + row) * DM + k0 + c4 * 8);
            CP_ASYNC16(sBase + (buf * 2 + 1) * GTILE + off,
                       W + (size_t)(bn + row) * DM + k0 + c4 * 8);
        }
        CP_COMMIT();
    };

    float4 acc[4][8];
#pragma unroll
    for (int i = 0; i < 4; i++)
#pragma unroll
        for (int j = 0; j < 8; j++) acc[i][j] = make_float4(0.f, 0.f, 0.f, 0.f);

    issue(0); issue(1); issue(2);

    for (int c = 0; c < 32; c++) {
        const int buf = c & 3;
        if (c < 30)       { CP_WAIT2(); }
        else if (c == 30) { CP_WAIT1(); }
        else              { CP_WAIT0(); }
        __syncthreads();               // buf c ready; readers of buf (c-1) done
        if (c + 3 < 32) issue(c + 3);  // writes buf (c-1)&3 — safe post-sync

        const uint32_t sA = sBase + buf * 2 * GTILE;
        const uint32_t sW = sA + GTILE;

        // B fragments: 8 n-tiles, each LDSM.x4 covers both k16 chunks
        uint32_t bf[8][4];
#pragma unroll
        for (int nt = 0; nt < 8; nt++) {
            const uint32_t baddr = sW + (uint32_t)(((wn + nt * 8 + (lane & 7)) * GST
                                     + ((lane >> 3) << 3)) * 2);
            LDSM_X4(bf[nt][0], bf[nt][1], bf[nt][2], bf[nt][3], baddr);
        }
        // A fragments: both k16 chunks hoisted (compile-time offsets)
        uint32_t af[2][4][4];
#pragma unroll
        for (int kc = 0; kc < 2; kc++)
#pragma unroll
            for (int mt = 0; mt < 4; mt++) {
                const uint32_t aaddr = sA + (uint32_t)(((wm + mt * 16 + (lane & 15)) * GST
                                         + kc * 16 + ((lane >> 4) << 3)) * 2);
                LDSM_X4(af[kc][mt][0], af[kc][mt][1], af[kc][mt][2], af[kc][mt][3], aaddr);
            }
        // 64 HMMAs, uninterrupted
#pragma unroll
        for (int kc = 0; kc < 2; kc++)
#pragma unroll
            for (int mt = 0; mt < 4; mt++)
#pragma unroll
                for (int nt = 0; nt < 8; nt++)
                    mma_f16(acc[mt][nt],
                            af[kc][mt][0], af[kc][mt][1],
                            af[kc][mt][2], af[kc][mt][3],
                            bf[nt][2 * kc], bf[nt][2 * kc + 1]);
    }

    // ---- epilogue ----
    const int lrow4 = lane >> 2;
    const int lcol4 = lane & 3;
#pragma unroll
    for (int mt = 0; mt < 4; mt++) {
        const int m0 = bm + wm + mt * 16 + lrow4;
#pragma unroll
        for (int nt = 0; nt < 8; nt++) {
            const int n0 = bn + wn + nt * 8 + lcol4 * 2;
            const float bb0 = __ldg(bias + n0);
            const float bb1 = __ldg(bias + n0 + 1);
            const float v00 = (acc[mt][nt].x + bb0) * oscale;
            const float v01 = (acc[mt][nt].y + bb1) * oscale;
            const float v10 = (acc[mt][nt].z + bb0) * oscale;
            const float v11 = (acc[mt][nt].w + bb1) * oscale;
            if (MODE == 0) {
                float* out = (float*)outp;
                *(float2*)(out + (size_t)m0 * DM + n0)       = make_float2(v00, v01);
                *(float2*)(out + (size_t)(m0 + 8) * DM + n0) = make_float2(v10, v11);
            } else {
                __half* out = (__half*)outp;
                const int h = n0 >> 6;
                const int d = n0 & 63;
                const int b_0 = m0 / TT,       t0 = m0 % TT;
                const int b_1 = (m0 + 8) / TT, t1 = (m0 + 8) % TT;
                *(uint32_t*)(out + ((size_t)(b_0 * NH + h) * TT + t0) * HD + d) = packh2(v00, v01);
                *(uint32_t*)(out + ((size_t)(b_1 * NH + h) * TT + t1) * HD + d) = packh2(v10, v11);
            }
        }
    }
}

// ---------------------------------------------------------------------------
// Causal flash attention, fp16 tensor cores. BQ=128 x BK=64, 256 thr = 8
// warps. P in registers. K/V triple-buffered cp.async. Base-2 softmax with
// scale pre-folded into Q; exp computed as ex2.approx.f16x2 (one MUFU per
// TWO elements, output IS the P fragment). Paired q-tiles: 512 CTAs x 34
// iterations, perfectly balanced.
// ---------------------------------------------------------------------------
#define HST 72
#define KH_OFF(buf) ((128 + (buf) * 2 * 64) * HST)
#define VH_OFF(buf) (KH_OFF(buf) + 64 * HST)
#define ATT_SMEM ((128 * HST + 3 * 2 * 64 * HST) * (int)sizeof(__half))  // 73728 B

__global__ __launch_bounds__(256, 2) void attn_kernel()
{
    extern __shared__ __half sh[];
    const int tid  = threadIdx.x;
    const int lane = tid & 31;
    const int w    = tid >> 5;

    const int p  = blockIdx.x;       // 0..7
    const int h  = blockIdx.y;
    const int b  = blockIdx.z;
    const size_t base = (size_t)(b * NH + h) * TT * HD;

    const uint32_t smem = smem_u32(sh);
    const int g = lane >> 2;
    const int ccol = 2 * (lane & 3);

    for (int tt = 0; tt < 2; tt++) {
        const int qt = tt ? (15 - p) : p;
        const int q0 = qt * 128;
        const int ntiles = 2 * qt + 2;

        auto issue_kv = [&](int j) {
            const int buf = j % 3;
#pragma unroll
            for (int i = 0; i < 2; i++) {
                const int idx = tid + i * 256;   // 64 rows x 8 x 16B
                const int row = idx >> 3;
                const int c8  = idx & 7;
                const uint32_t off = (uint32_t)((row * HST + c8 * 8) * 2);
                CP_ASYNC16(smem + KH_OFF(buf) * 2 + off,
                           g_Kh + base + (size_t)(j * 64 + row) * HD + c8 * 8);
                CP_ASYNC16(smem + VH_OFF(buf) * 2 + off,
                           g_Vh + base + (size_t)(j * 64 + row) * HD + c8 * 8);
            }
            CP_COMMIT();
        };

        issue_kv(0);
        issue_kv(1);   // ntiles >= 2 always

        // ---- Load Q tile (128 x 64 halves) ----
#pragma unroll
        for (int i = 0; i < 4; i++) {
            const int idx = tid + i * 256;
            const int q   = idx >> 3;
            const int c8  = idx & 7;
            uint4 v = *(const uint4*)(g_Qh + base + (size_t)(q0 + q) * HD + c8 * 8);
            *(uint4*)&sh[q * HST + c8 * 8] = v;
        }
        __syncthreads();

        uint32_t qa[4][4];
        {
            const uint32_t rbase = smem + (uint32_t)(((w * 16 + (lane & 15)) * HST
                                   + ((lane >> 4) << 3)) * 2);
#pragma unroll
            for (int kk = 0; kk < 4; kk++)
                LDSM_X4(qa[kk][0], qa[kk][1], qa[kk][2], qa[kk][3], rbase + kk * 32);
        }

        float4 o[8];
#pragma unroll
        for (int i = 0; i < 8; i++) o[i] = make_float4(0.f, 0.f, 0.f, 0.f);
        float m0 = -1e30f, m1 = -1e30f, l0 = 0.f, l1 = 0.f;

        const int qrow0 = q0 + w * 16 + g;
        const int qrow1 = qrow0 + 8;

        for (int j = 0; j < ntiles; j++) {
            const int buf = j % 3;
            if (j + 1 < ntiles) { CP_WAIT1(); } else { CP_WAIT0(); }
            __syncthreads();                      // buf j ready; readers of j-1 done
            if (j + 2 < ntiles) issue_kv(j + 2);  // writes buf (j-1)%3 — safe

            const uint32_t sK = smem + KH_OFF(buf) * 2;
            const uint32_t sV = smem + VH_OFF(buf) * 2;

            // ---- S = Q @ K^T (already in base-2 scaled domain via Q) ----
            float4 s[8];
#pragma unroll
            for (int kn = 0; kn < 8; kn++) s[kn] = make_float4(0.f, 0.f, 0.f, 0.f);
#pragma unroll
            for (int kn = 0; kn < 8; kn++) {
                uint32_t kb[2][4];
                const uint32_t kaddr = sK + (uint32_t)(((kn * 8 + (lane & 7)) * HST
                                       + ((lane >> 3) << 3)) * 2);
                LDSM_X4(kb[0][0], kb[0][1], kb[0][2], kb[0][3], kaddr);
                LDSM_X4(kb[1][0], kb[1][1], kb[1][2], kb[1][3], kaddr + 64);
#pragma unroll
                for (int kk = 0; kk < 4; kk++)
                    mma_f16(s[kn], qa[kk][0], qa[kk][1], qa[kk][2], qa[kk][3],
                            kb[kk >> 1][2 * (kk & 1)], kb[kk >> 1][2 * (kk & 1) + 1]);
            }

            // ---- causal mask (last two key tiles only) ----
            const bool need_mask = (j >= 2 * qt);
            if (need_mask) {
#pragma unroll
                for (int kn = 0; kn < 8; kn++) {
                    const int col = j * 64 + kn * 8 + ccol;
                    if (col     > qrow0) s[kn].x = -1e30f;
                    if (col + 1 > qrow0) s[kn].y = -1e30f;
                    if (col     > qrow1) s[kn].z = -1e30f;
                    if (col + 1 > qrow1) s[kn].w = -1e30f;
                }
            }

            // ---- online softmax (fp32 max, fp16x2 exp) ----
            float mx0 = -1e30f, mx1 = -1e30f;
#pragma unroll
            for (int kn = 0; kn < 8; kn++) {
                mx0 = fmaxf(mx0, fmaxf(s[kn].x, s[kn].y));
                mx1 = fmaxf(mx1, fmaxf(s[kn].z, s[kn].w));
            }
            mx0 = fmaxf(mx0, __shfl_xor_sync(0xffffffffu, mx0, 1));
            mx0 = fmaxf(mx0, __shfl_xor_sync(0xffffffffu, mx0, 2));
            mx1 = fmaxf(mx1, __shfl_xor_sync(0xffffffffu, mx1, 1));
            mx1 = fmaxf(mx1, __shfl_xor_sync(0xffffffffu, mx1, 2));
            const float mn0 = fmaxf(m0, mx0);
            const float mn1 = fmaxf(m1, mx1);

            // P fragments straight from fp16x2 exp; row sums from the same
            // fp16 values (exactly consistent with the PV MMA operands).
            uint32_t pa[4][4];
            float ps0 = 0.f, ps1 = 0.f;
#pragma unroll
            for (int kn = 0; kn < 8; kn++) {
                const uint32_t e0 = ex2_f16x2(s[kn].x - mn0, s[kn].y - mn0);
                const uint32_t e1 = ex2_f16x2(s[kn].z - mn1, s[kn].w - mn1);
                pa[kn >> 1][2 * (kn & 1)]     = e0;
                pa[kn >> 1][2 * (kn & 1) + 1] = e1;
                const float2 f0 = h2_to_f2(e0);
                const float2 f1 = h2_to_f2(e1);
                ps0 += f0.x + f0.y;
                ps1 += f1.x + f1.y;
            }
            ps0 += __shfl_xor_sync(0xffffffffu, ps0, 1);
            ps0 += __shfl_xor_sync(0xffffffffu, ps0, 2);
            ps1 += __shfl_xor_sync(0xffffffffu, ps1, 1);
            ps1 += __shfl_xor_sync(0xffffffffu, ps1, 2);

            const float corr0 = exp2f(m0 - mn0);
            const float corr1 = exp2f(m1 - mn1);
            l0 = l0 * corr0 + ps0;  m0 = mn0;
            l1 = l1 * corr1 + ps1;  m1 = mn1;
#pragma unroll
            for (int i = 0; i < 8; i++) {
                o[i].x *= corr0; o[i].y *= corr0;
                o[i].z *= corr1; o[i].w *= corr1;
            }

            // ---- O += P @ V ----
#pragma unroll
            for (int vn = 0; vn < 8; vn++) {
                uint32_t vb[2][4];
#pragma unroll
                for (int c = 0; c < 2; c++) {
                    const uint32_t vaddr = sV + (uint32_t)(((c * 32 + (lane & 31)) * HST
                                            + vn * 8) * 2);
                    LDSM_X4_T(vb[c][0], vb[c][1], vb[c][2], vb[c][3], vaddr);
                }
#pragma unroll
                for (int t = 0; t < 4; t++)
                    mma_f16(o[vn], pa[t][0], pa[t][1], pa[t][2], pa[t][3],
                            vb[t >> 1][2 * (t & 1)], vb[t >> 1][2 * (t & 1) + 1]);
            }
        }

        // ---- normalize + write ctx (B,T,D) as half ----
        const float inv0 = 1.f / l0;
        const float inv1 = 1.f / l1;
#pragma unroll
        for (int vn = 0; vn < 8; vn++) {
            const int d = vn * 8 + ccol;
            *(uint32_t*)(g_Ch + ((size_t)(b * TT + qrow0)) * DM + h * HD + d) =
                packh2(o[vn].x * inv0, o[vn].y * inv0);
            *(uint32_t*)(g_Ch + ((size_t)(b * TT + qrow1)) * DM + h * HD + d) =
                packh2(o[vn].z * inv1, o[vn].w * inv1);
        }
        __syncthreads();   // all smem reads done before next tile reuses buffers
    }
}

// ---------------------------------------------------------------------------
extern "C" void kernel_launch(void* const* d_in, const int* in_sizes, int n_in,
                              void* d_out, int out_size)
{
    const float* x  = (const float*)d_in[0];
    const float* Wq = (const float*)d_in[1];
    const float* bq = (const float*)d_in[2];
    const float* Wk = (const float*)d_in[3];
    const float* bk = (const float*)d_in[4];
    const float* Wv = (const float*)d_in[5];
    const float* bv = (const float*)d_in[6];
    const float* Wo = (const float*)d_in[7];
    const float* bo = (const float*)d_in[8];
    float* out = (float*)d_out;

    __half *Xp, *Qp, *Kp, *Vp, *Cp, *Wqp, *Wkp, *Wvp, *Wop;
    cudaGetSymbolAddress((void**)&Xp,  g_Xh);
    cudaGetSymbolAddress((void**)&Qp,  g_Qh);
    cudaGetSymbolAddress((void**)&Kp,  g_Kh);
    cudaGetSymbolAddress((void**)&Vp,  g_Vh);
    cudaGetSymbolAddress((void**)&Cp,  g_Ch);
    cudaGetSymbolAddress((void**)&Wqp, g_Wqh);
    cudaGetSymbolAddress((void**)&Wkp, g_Wkh);
    cudaGetSymbolAddress((void**)&Wvp, g_Wvh);
    cudaGetSymbolAddress((void**)&Wop, g_Woh);

    cudaFuncSetAttribute(gemm_h<0>, cudaFuncAttributeMaxDynamicSharedMemorySize, GEMM_SMEM);
    cudaFuncSetAttribute(gemm_h<1>, cudaFuncAttributeMaxDynamicSharedMemorySize, GEMM_SMEM);
    cudaFuncSetAttribute(attn_kernel, cudaFuncAttributeMaxDynamicSharedMemorySize, ATT_SMEM);

    // ---- preconvert to half (x + 4 weights, one launch) ----
    const size_t ntot = (size_t)MT * DM + 4 * (size_t)DM * DM;  // 12.58M
    f2h_all<<<(int)(ntot / 8 / 256), 256>>>(x, Wq, Wk, Wv, Wo);

    // ---- fused QKV projections (Q output pre-scaled by SCL2) ----
    dim3 gq(DM / 128, MT / 128, 3);
    gemm_h<1><<<gq, 128, GEMM_SMEM>>>(Xp, Wqp, Wkp, Wvp, bq, bk, bv, Qp, Kp, Vp);

    // ---- attention (paired q-tiles, perfectly balanced) ----
    dim3 agrid(8, NH, BB);            // 512 CTAs x 34 iterations each
    attn_kernel<<<agrid, 256, ATT_SMEM>>>();

    // ---- output projection ----
    dim3 go(DM / 128, MT / 128, 1);
    gemm_h<0><<<go, 128, GEMM_SMEM>>>(Cp, Wop, Wop, Wop, bo, bo, bo, out, out, out);
}